// round 14
// baseline (speedup 1.0000x reference)
#include <cuda_runtime.h>
#include <cstdint>

#define NB 32
#define NT 512
#define ND 512
#define NH 1024
#define NM (NB*NT)   // 16384 rows

typedef unsigned long long ull;

// ---- scratch (device globals; no runtime allocation allowed) ----
__device__ float         g_h1[(size_t)NM * NH];   // 64 MB fc1 raw output
__device__ unsigned char g_s1[(size_t)NM * NH];   // 16 MB spikes layer 1
__device__ float         g_y [(size_t)NM * ND];   // 32 MB fc2+ln2 out
__device__ float         g_w2t[(size_t)NH * ND];  //  2 MB w2 transposed to [H, D]
__device__ float         g_mean[NM];              // ln1 row means
__device__ float         g_inv [NM];              // ln1 row inv-std

// ---- packed fp32x2 helpers (Blackwell FFMA2, identical per-lane fp32 rounding) ----
__device__ __forceinline__ ull pack2(float lo, float hi) {
    ull r;
    asm("mov.b64 %0, {%1, %2};" : "=l"(r)
        : "r"(__float_as_uint(lo)), "r"(__float_as_uint(hi)));
    return r;
}
__device__ __forceinline__ void unpack2(ull v, float& lo, float& hi) {
    unsigned a, b;
    asm("mov.b64 {%0, %1}, %2;" : "=r"(a), "=r"(b) : "l"(v));
    lo = __uint_as_float(a); hi = __uint_as_float(b);
}
__device__ __forceinline__ ull fma2(ull a, ull b, ull c) {
    ull d;
    asm("fma.rn.f32x2 %0, %1, %2, %3;" : "=l"(d) : "l"(a), "l"(b), "l"(c));
    return d;
}

// ============================================================================
// GEMM1 (R12/R13-verified): g_h1[m,n] = sum_k x[m,k]*w1[n,k] + b1[n]
// ============================================================================
#define GEMM_STORE(BUF)                                                        \
    do {                                                                       \
        As[BUF][lk + 0][lm] = pa0.x; As[BUF][lk + 1][lm] = pa0.y;              \
        As[BUF][lk + 2][lm] = pa0.z; As[BUF][lk + 3][lm] = pa0.w;              \
        As[BUF][lk + 0][lm + 64] = pa1.x; As[BUF][lk + 1][lm + 64] = pa1.y;    \
        As[BUF][lk + 2][lm + 64] = pa1.z; As[BUF][lk + 3][lm + 64] = pa1.w;    \
        Bs[BUF][lk + 0][lm] = pb0.x; Bs[BUF][lk + 1][lm] = pb0.y;              \
        Bs[BUF][lk + 2][lm] = pb0.z; Bs[BUF][lk + 3][lm] = pb0.w;              \
        Bs[BUF][lk + 0][lm + 64] = pb1.x; Bs[BUF][lk + 1][lm + 64] = pb1.y;    \
        Bs[BUF][lk + 2][lm + 64] = pb1.z; Bs[BUF][lk + 3][lm + 64] = pb1.w;    \
    } while (0)

#define GEMM_LOAD(KT)                                                          \
    do {                                                                       \
        const float* Ap2 = Ap + (KT) * 16;                                     \
        const float* Bp2 = Bp + (KT) * 16;                                     \
        pa0 = *(const float4*)(Ap2);                                           \
        pa1 = *(const float4*)(Ap2 + (size_t)64 * ND);                         \
        pb0 = *(const float4*)(Bp2);                                           \
        pb1 = *(const float4*)(Bp2 + (size_t)64 * ND);                         \
    } while (0)

#define GEMM_COMPUTE(BUF)                                                      \
    _Pragma("unroll")                                                          \
    for (int kk = 0; kk < 16; kk++) {                                          \
        float4 a0 = *(const float4*)&As[BUF][kk][ty * 8];                      \
        float4 a1 = *(const float4*)&As[BUF][kk][ty * 8 + 4];                  \
        ulonglong2 bl0 = *(const ulonglong2*)&Bs[BUF][kk][tx * 8];             \
        ulonglong2 bl1 = *(const ulonglong2*)&Bs[BUF][kk][tx * 8 + 4];         \
        float av[8] = {a0.x, a0.y, a0.z, a0.w, a1.x, a1.y, a1.z, a1.w};        \
        _Pragma("unroll")                                                      \
        for (int i = 0; i < 8; i++) {                                          \
            ull aa = pack2(av[i], av[i]);                                      \
            acc[i][0] = fma2(aa, bl0.x, acc[i][0]);                            \
            acc[i][1] = fma2(aa, bl0.y, acc[i][1]);                            \
            acc[i][2] = fma2(aa, bl1.x, acc[i][2]);                            \
            acc[i][3] = fma2(aa, bl1.y, acc[i][3]);                            \
        }                                                                      \
    }

__global__ __launch_bounds__(256, 2) void gemm1_kernel(const float* __restrict__ A,
                                                       const float* __restrict__ W,
                                                       const float* __restrict__ bias) {
    __shared__ __align__(16) float As[2][16][132];
    __shared__ __align__(16) float Bs[2][16][132];
    const int tid  = threadIdx.x;
    const int row0 = blockIdx.y * 128;
    const int col0 = blockIdx.x * 128;
    const int tx = tid & 15;
    const int ty = tid >> 4;
    const int lm = tid >> 2;
    const int lk = (tid & 3) * 4;

    const float* Ap = A + (size_t)(row0 + lm) * ND + lk;
    const float* Bp = W + (size_t)(col0 + lm) * ND + lk;

    ull acc[8][4];
#pragma unroll
    for (int i = 0; i < 8; i++)
#pragma unroll
        for (int j = 0; j < 4; j++) acc[i][j] = 0ull;

    float4 pa0, pa1, pb0, pb1;
    GEMM_LOAD(0);
    GEMM_STORE(0);
    GEMM_LOAD(1);
    __syncthreads();

#pragma unroll 1
    for (int kt = 0; kt < 32; kt += 2) {
        GEMM_STORE(1);
        if (kt + 2 < 32) GEMM_LOAD(kt + 2);
        GEMM_COMPUTE(0);
        __syncthreads();
        if (kt + 2 < 32) {
            GEMM_STORE(0);
            if (kt + 3 < 32) GEMM_LOAD(kt + 3);
        }
        GEMM_COMPUTE(1);
        __syncthreads();
    }

    float bv[8];
#pragma unroll
    for (int j = 0; j < 8; j++) bv[j] = bias[col0 + tx * 8 + j];
#pragma unroll
    for (int i = 0; i < 8; i++) {
        float o[8];
        unpack2(acc[i][0], o[0], o[1]);
        unpack2(acc[i][1], o[2], o[3]);
        unpack2(acc[i][2], o[4], o[5]);
        unpack2(acc[i][3], o[6], o[7]);
#pragma unroll
        for (int j = 0; j < 8; j++) o[j] += bv[j];
        float* cp = g_h1 + (size_t)(row0 + ty * 8 + i) * NH + col0 + tx * 8;
        ((float4*)cp)[0] = make_float4(o[0], o[1], o[2], o[3]);
        ((float4*)cp)[1] = make_float4(o[4], o[5], o[6], o[7]);
    }
}

// ============================================================================
// block-wide reduction (blockDim multiple of 32, <= 256)
// ============================================================================
__device__ __forceinline__ float block_reduce_sum(float val) {
    __shared__ float sm[32];
    const int tid = threadIdx.x;
#pragma unroll
    for (int o = 16; o; o >>= 1) val += __shfl_down_sync(0xffffffffu, val, o);
    if ((tid & 31) == 0) sm[tid >> 5] = val;
    __syncthreads();
    if (tid < 32) {
        const int nw = (blockDim.x + 31) >> 5;
        float v = (tid < nw) ? sm[tid] : 0.f;
#pragma unroll
        for (int o = 4; o; o >>= 1) v += __shfl_down_sync(0xffffffffu, v, o);
        if (tid == 0) sm[0] = v;
    }
    __syncthreads();
    float r = sm[0];
    __syncthreads();
    return r;
}

// ============================================================================
// LN1 stats (warp-per-row, R13-verified) + FOLDED w2 transpose.
// Blocks [0, NM/8): stats. Blocks [NM/8, NM/8+512): transpose one 32x32 tile.
// ============================================================================
__global__ __launch_bounds__(256) void ln1_stats_kernel(const float* __restrict__ w2) {
    __shared__ float tile[32][33];
    if (blockIdx.x >= NM / 8) {
        // ---- w2 [D,H] -> g_w2t [H,D], 32x32 tile, 256 threads ----
        const int t = blockIdx.x - NM / 8;          // 0..511
        const int h0 = (t & 31) * 32;               // NH/32 = 32 tiles
        const int d0 = (t >> 5) * 32;               // ND/32 = 16 tiles
        const int tx = threadIdx.x & 31;
        const int ty = threadIdx.x >> 5;            // 0..7
#pragma unroll
        for (int r = 0; r < 4; r++)
            tile[ty + r * 8][tx] = w2[(size_t)(d0 + ty + r * 8) * NH + h0 + tx];
        __syncthreads();
#pragma unroll
        for (int r = 0; r < 4; r++)
            g_w2t[(size_t)(h0 + ty + r * 8) * ND + d0 + tx] = tile[tx][ty + r * 8];
        return;
    }

    const int wid = threadIdx.x >> 5;               // 0..7
    const int lane = threadIdx.x & 31;
    const int row = blockIdx.x * 8 + wid;
    const float4* p = (const float4*)(g_h1 + (size_t)row * NH);

    float4 v[8];
#pragma unroll
    for (int j = 0; j < 8; j++) v[j] = p[lane + j * 32];

    float s = 0.f;
#pragma unroll
    for (int j = 0; j < 8; j++) s += (v[j].x + v[j].y) + (v[j].z + v[j].w);
#pragma unroll
    for (int o = 16; o; o >>= 1) s += __shfl_xor_sync(0xffffffffu, s, o);
    const float mean = s * (1.0f / NH);

    float sq = 0.f;
#pragma unroll
    for (int j = 0; j < 8; j++) {
        float d0 = v[j].x - mean, d1 = v[j].y - mean;
        float d2 = v[j].z - mean, d3 = v[j].w - mean;
        sq += (d0 * d0 + d1 * d1) + (d2 * d2 + d3 * d3);
    }
#pragma unroll
    for (int o = 16; o; o >>= 1) sq += __shfl_xor_sync(0xffffffffu, sq, o);
    const float inv = 1.0f / sqrtf(sq * (1.0f / NH) + 1e-5f);

    if (lane == 0) { g_mean[row] = mean; g_inv[row] = inv; }
}

// ============================================================================
// LIF layer 1 with inline LayerNorm, SOFTWARE-PIPELINED (R12-verified).
// ============================================================================
__global__ __launch_bounds__(128) void lif1_kernel(const float* __restrict__ g1,
                                                   const float* __restrict__ be1) {
    const int idx = blockIdx.x * 128 + threadIdx.x;   // NB*NH = 32768
    const int b = idx >> 10;
    const int h = idx & (NH - 1);
    const int tid = threadIdx.x;

    __shared__ float s_mean[NT];
    __shared__ float s_inv[NT];
#pragma unroll
    for (int t = tid; t < NT; t += 128) {
        s_mean[t] = g_mean[b * NT + t];
        s_inv[t]  = g_inv [b * NT + t];
    }
    __syncthreads();

    const float gh  = g1[h];
    const float beh = be1[h];
    const float* p = g_h1 + (size_t)b * NT * NH + h;
    unsigned char* q = g_s1 + (size_t)b * NT * NH + h;

    float xa[16], xb[16];
#pragma unroll
    for (int i = 0; i < 16; i++) xa[i] = p[(size_t)i * NH];

    float v = 0.f;
#pragma unroll 1
    for (int t0 = 0; t0 < NT; t0 += 32) {
#pragma unroll
        for (int i = 0; i < 16; i++) xb[i] = p[(size_t)(t0 + 16 + i) * NH];

        unsigned char sb[16];
#pragma unroll
        for (int i = 0; i < 16; i++) {
            float d = xa[i] - s_mean[t0 + i];
            float val = d * s_inv[t0 + i] * gh + beh;
            v = v + (val - v) * 0.5f;       // TAU = 2
            bool sp = (v >= 1.0f);          // V_TH = 1
            sb[i] = sp ? (unsigned char)1 : (unsigned char)0;
            v = sp ? 0.f : v;               // hard reset
        }
#pragma unroll
        for (int i = 0; i < 16; i++) q[(size_t)(t0 + i) * NH] = sb[i];

        if (t0 + 32 < NT) {
#pragma unroll
            for (int i = 0; i < 16; i++) xa[i] = p[(size_t)(t0 + 32 + i) * NH];
        }

#pragma unroll
        for (int i = 0; i < 16; i++) {
            float d = xb[i] - s_mean[t0 + 16 + i];
            float val = d * s_inv[t0 + 16 + i] * gh + beh;
            v = v + (val - v) * 0.5f;
            bool sp = (v >= 1.0f);
            sb[i] = sp ? (unsigned char)1 : (unsigned char)0;
            v = sp ? 0.f : v;
        }
#pragma unroll
        for (int i = 0; i < 16; i++) q[(size_t)(t0 + 16 + i) * NH] = sb[i];
    }
}

// ============================================================================
// fc2 (sparse gmem gather, L1-resident w2t) + fused LayerNorm2 (R4-verified).
// ============================================================================
__global__ __launch_bounds__(128) void fc2ln2_kernel(const float* __restrict__ b2,
                                                     const float* __restrict__ g2,
                                                     const float* __restrict__ be2) {
    const int row = blockIdx.x;
    const int tid = threadIdx.x;
    const unsigned char* srow = g_s1 + (size_t)row * NH;

    ull m8 = ((const ull*)srow)[tid];           // 8 spike bytes
    int c = __popcll(m8);
    int pre = c;
#pragma unroll
    for (int o = 1; o < 32; o <<= 1) {
        int n = __shfl_up_sync(0xffffffffu, pre, o);
        if ((tid & 31) >= o) pre += n;
    }
    __shared__ int wsum[4];
    __shared__ unsigned short list[NH];
    __shared__ int s_total;
    if ((tid & 31) == 31) wsum[tid >> 5] = pre;
    __syncthreads();
    int base = 0;
#pragma unroll
    for (int w = 0; w < 4; w++)
        if (w < (tid >> 5)) base += wsum[w];
    int off = base + pre - c;
#pragma unroll
    for (int k = 0; k < 8; k++)
        if ((m8 >> (8 * k)) & 1ull) list[off++] = (unsigned short)(tid * 8 + k);
    if (tid == 127) s_total = base + pre;
    __syncthreads();

    const int cnt = s_total;
    const float* wbase = g_w2t + tid * 4;
    float4 acc = make_float4(0.f, 0.f, 0.f, 0.f);
    int i = 0;
    for (; i + 4 <= cnt; i += 4) {
        int h0 = list[i], h1 = list[i + 1], h2 = list[i + 2], h3 = list[i + 3];
        float4 w0 = *(const float4*)(wbase + (size_t)h0 * ND);
        float4 w1 = *(const float4*)(wbase + (size_t)h1 * ND);
        float4 w2v = *(const float4*)(wbase + (size_t)h2 * ND);
        float4 w3 = *(const float4*)(wbase + (size_t)h3 * ND);
        acc.x += w0.x; acc.y += w0.y; acc.z += w0.z; acc.w += w0.w;
        acc.x += w1.x; acc.y += w1.y; acc.z += w1.z; acc.w += w1.w;
        acc.x += w2v.x; acc.y += w2v.y; acc.z += w2v.z; acc.w += w2v.w;
        acc.x += w3.x; acc.y += w3.y; acc.z += w3.z; acc.w += w3.w;
    }
    for (; i < cnt; i++) {
        float4 w0 = *(const float4*)(wbase + (size_t)list[i] * ND);
        acc.x += w0.x; acc.y += w0.y; acc.z += w0.z; acc.w += w0.w;
    }
    float4 bb = ((const float4*)b2)[tid];
    acc.x += bb.x; acc.y += bb.y; acc.z += bb.z; acc.w += bb.w;

    // ---- fused LayerNorm2 ----
    float s = (acc.x + acc.y) + (acc.z + acc.w);
    float total = block_reduce_sum(s);
    float mean = total * (1.0f / ND);
    float d0 = acc.x - mean, d1 = acc.y - mean, d2 = acc.z - mean, d3 = acc.w - mean;
    float sq = (d0 * d0 + d1 * d1) + (d2 * d2 + d3 * d3);
    float tot2 = block_reduce_sum(sq);
    float inv = 1.0f / sqrtf(tot2 * (1.0f / ND) + 1e-5f);
    float4 gg = ((const float4*)g2)[tid];
    float4 bv = ((const float4*)be2)[tid];
    float4 o;
    o.x = d0 * inv * gg.x + bv.x;
    o.y = d1 * inv * gg.y + bv.y;
    o.z = d2 * inv * gg.z + bv.z;
    o.w = d3 * inv * gg.w + bv.w;
    ((float4*)(g_y + (size_t)row * ND))[tid] = o;
}

// ============================================================================
// LIF layer 2 + residual, TRIPLE-BUFFERED pipeline (prefetch distance 2).
// Fully unrolled chunk loop -> all buffer indices compile-time.
// Per-element arithmetic order identical -> bitwise-exact.
// ============================================================================
__global__ __launch_bounds__(64) void lif2_kernel(const float* __restrict__ x,
                                                  float* __restrict__ out) {
    const int idx = blockIdx.x * 64 + threadIdx.x;    // NB*ND = 16384
    const int b = idx >> 9;
    const int d = idx & (ND - 1);
    const float* py = g_y + (size_t)b * NT * ND + d;
    const float* px = x + (size_t)b * NT * ND + d;
    float* po = out + (size_t)b * NT * ND + d;

    float ybuf[3][16], xbuf[3][16];
#pragma unroll
    for (int i = 0; i < 16; i++) ybuf[0][i] = py[(size_t)i * ND];
#pragma unroll
    for (int i = 0; i < 16; i++) xbuf[0][i] = px[(size_t)i * ND];
#pragma unroll
    for (int i = 0; i < 16; i++) ybuf[1][i] = py[(size_t)(16 + i) * ND];
#pragma unroll
    for (int i = 0; i < 16; i++) xbuf[1][i] = px[(size_t)(16 + i) * ND];

    float v = 0.f;
#pragma unroll
    for (int c = 0; c < 32; c++) {          // 32 chunks of 16, fully unrolled
        if (c + 2 < 32) {
            const int nxt = (c + 2) % 3;
#pragma unroll
            for (int i = 0; i < 16; i++)
                ybuf[nxt][i] = py[(size_t)((c + 2) * 16 + i) * ND];
#pragma unroll
            for (int i = 0; i < 16; i++)
                xbuf[nxt][i] = px[(size_t)((c + 2) * 16 + i) * ND];
        }
        const int cur = c % 3;
        float ob[16];
#pragma unroll
        for (int i = 0; i < 16; i++) {
            v = v + (ybuf[cur][i] - v) * 0.5f;
            bool sp = (v >= 1.0f);
            ob[i] = xbuf[cur][i] + (sp ? 1.0f : 0.0f);
            v = sp ? 0.f : v;
        }
#pragma unroll
        for (int i = 0; i < 16; i++) po[(size_t)(c * 16 + i) * ND] = ob[i];
    }
}

// ============================================================================
extern "C" void kernel_launch(void* const* d_in, const int* in_sizes, int n_in,
                              void* d_out, int out_size) {
    const float* x   = (const float*)d_in[0];
    const float* w1  = (const float*)d_in[1];
    const float* b1  = (const float*)d_in[2];
    const float* g1  = (const float*)d_in[3];
    const float* be1 = (const float*)d_in[4];
    const float* w2  = (const float*)d_in[5];
    const float* b2  = (const float*)d_in[6];
    const float* g2  = (const float*)d_in[7];
    const float* be2 = (const float*)d_in[8];
    float* out = (float*)d_out;

    gemm1_kernel<<<dim3(NH / 128, NM / 128), 256>>>(x, w1, b1);
    ln1_stats_kernel<<<NM / 8 + 512, 256>>>(w2);   // stats + folded transpose
    lif1_kernel<<<(NB * NH) / 128, 128>>>(g1, be1);
    fc2ln2_kernel<<<NM, 128>>>(b2, g2, be2);
    lif2_kernel<<<(NB * ND) / 64, 64>>>(x, out);
}

// round 15
// speedup vs baseline: 1.0262x; 1.0262x over previous
#include <cuda_runtime.h>
#include <cstdint>

#define NB 32
#define NT 512
#define ND 512
#define NH 1024
#define NM (NB*NT)   // 16384 rows

typedef unsigned long long ull;

// ---- scratch (device globals; no runtime allocation allowed) ----
__device__ float         g_h1[(size_t)NM * NH];   // 64 MB fc1 raw output
__device__ unsigned char g_s1[(size_t)NM * NH];   // 16 MB spikes layer 1
__device__ float         g_y [(size_t)NM * ND];   // 32 MB fc2+ln2 out
__device__ float         g_w2t[(size_t)NH * ND];  //  2 MB w2 transposed to [H, D]
__device__ float         g_mean[NM];              // ln1 row means
__device__ float         g_inv [NM];              // ln1 row inv-std

// ---- packed fp32x2 helpers (Blackwell FFMA2, identical per-lane fp32 rounding) ----
__device__ __forceinline__ ull pack2(float lo, float hi) {
    ull r;
    asm("mov.b64 %0, {%1, %2};" : "=l"(r)
        : "r"(__float_as_uint(lo)), "r"(__float_as_uint(hi)));
    return r;
}
__device__ __forceinline__ void unpack2(ull v, float& lo, float& hi) {
    unsigned a, b;
    asm("mov.b64 {%0, %1}, %2;" : "=r"(a), "=r"(b) : "l"(v));
    lo = __uint_as_float(a); hi = __uint_as_float(b);
}
__device__ __forceinline__ ull fma2(ull a, ull b, ull c) {
    ull d;
    asm("fma.rn.f32x2 %0, %1, %2, %3;" : "=l"(d) : "l"(a), "l"(b), "l"(c));
    return d;
}

// ============================================================================
// GEMM1 (R12/R13-verified): g_h1[m,n] = sum_k x[m,k]*w1[n,k] + b1[n]
// ============================================================================
#define GEMM_STORE(BUF)                                                        \
    do {                                                                       \
        As[BUF][lk + 0][lm] = pa0.x; As[BUF][lk + 1][lm] = pa0.y;              \
        As[BUF][lk + 2][lm] = pa0.z; As[BUF][lk + 3][lm] = pa0.w;              \
        As[BUF][lk + 0][lm + 64] = pa1.x; As[BUF][lk + 1][lm + 64] = pa1.y;    \
        As[BUF][lk + 2][lm + 64] = pa1.z; As[BUF][lk + 3][lm + 64] = pa1.w;    \
        Bs[BUF][lk + 0][lm] = pb0.x; Bs[BUF][lk + 1][lm] = pb0.y;              \
        Bs[BUF][lk + 2][lm] = pb0.z; Bs[BUF][lk + 3][lm] = pb0.w;              \
        Bs[BUF][lk + 0][lm + 64] = pb1.x; Bs[BUF][lk + 1][lm + 64] = pb1.y;    \
        Bs[BUF][lk + 2][lm + 64] = pb1.z; Bs[BUF][lk + 3][lm + 64] = pb1.w;    \
    } while (0)

#define GEMM_LOAD(KT)                                                          \
    do {                                                                       \
        const float* Ap2 = Ap + (KT) * 16;                                     \
        const float* Bp2 = Bp + (KT) * 16;                                     \
        pa0 = *(const float4*)(Ap2);                                           \
        pa1 = *(const float4*)(Ap2 + (size_t)64 * ND);                         \
        pb0 = *(const float4*)(Bp2);                                           \
        pb1 = *(const float4*)(Bp2 + (size_t)64 * ND);                         \
    } while (0)

#define GEMM_COMPUTE(BUF)                                                      \
    _Pragma("unroll")                                                          \
    for (int kk = 0; kk < 16; kk++) {                                          \
        float4 a0 = *(const float4*)&As[BUF][kk][ty * 8];                      \
        float4 a1 = *(const float4*)&As[BUF][kk][ty * 8 + 4];                  \
        ulonglong2 bl0 = *(const ulonglong2*)&Bs[BUF][kk][tx * 8];             \
        ulonglong2 bl1 = *(const ulonglong2*)&Bs[BUF][kk][tx * 8 + 4];         \
        float av[8] = {a0.x, a0.y, a0.z, a0.w, a1.x, a1.y, a1.z, a1.w};        \
        _Pragma("unroll")                                                      \
        for (int i = 0; i < 8; i++) {                                          \
            ull aa = pack2(av[i], av[i]);                                      \
            acc[i][0] = fma2(aa, bl0.x, acc[i][0]);                            \
            acc[i][1] = fma2(aa, bl0.y, acc[i][1]);                            \
            acc[i][2] = fma2(aa, bl1.x, acc[i][2]);                            \
            acc[i][3] = fma2(aa, bl1.y, acc[i][3]);                            \
        }                                                                      \
    }

__global__ __launch_bounds__(256, 2) void gemm1_kernel(const float* __restrict__ A,
                                                       const float* __restrict__ W,
                                                       const float* __restrict__ bias) {
    __shared__ __align__(16) float As[2][16][132];
    __shared__ __align__(16) float Bs[2][16][132];
    const int tid  = threadIdx.x;
    const int row0 = blockIdx.y * 128;
    const int col0 = blockIdx.x * 128;
    const int tx = tid & 15;
    const int ty = tid >> 4;
    const int lm = tid >> 2;
    const int lk = (tid & 3) * 4;

    const float* Ap = A + (size_t)(row0 + lm) * ND + lk;
    const float* Bp = W + (size_t)(col0 + lm) * ND + lk;

    ull acc[8][4];
#pragma unroll
    for (int i = 0; i < 8; i++)
#pragma unroll
        for (int j = 0; j < 4; j++) acc[i][j] = 0ull;

    float4 pa0, pa1, pb0, pb1;
    GEMM_LOAD(0);
    GEMM_STORE(0);
    GEMM_LOAD(1);
    __syncthreads();

#pragma unroll 1
    for (int kt = 0; kt < 32; kt += 2) {
        GEMM_STORE(1);
        if (kt + 2 < 32) GEMM_LOAD(kt + 2);
        GEMM_COMPUTE(0);
        __syncthreads();
        if (kt + 2 < 32) {
            GEMM_STORE(0);
            if (kt + 3 < 32) GEMM_LOAD(kt + 3);
        }
        GEMM_COMPUTE(1);
        __syncthreads();
    }

    float bv[8];
#pragma unroll
    for (int j = 0; j < 8; j++) bv[j] = bias[col0 + tx * 8 + j];
#pragma unroll
    for (int i = 0; i < 8; i++) {
        float o[8];
        unpack2(acc[i][0], o[0], o[1]);
        unpack2(acc[i][1], o[2], o[3]);
        unpack2(acc[i][2], o[4], o[5]);
        unpack2(acc[i][3], o[6], o[7]);
#pragma unroll
        for (int j = 0; j < 8; j++) o[j] += bv[j];
        float* cp = g_h1 + (size_t)(row0 + ty * 8 + i) * NH + col0 + tx * 8;
        ((float4*)cp)[0] = make_float4(o[0], o[1], o[2], o[3]);
        ((float4*)cp)[1] = make_float4(o[4], o[5], o[6], o[7]);
    }
}

// ============================================================================
// block-wide reduction (blockDim multiple of 32, <= 256)
// ============================================================================
__device__ __forceinline__ float block_reduce_sum(float val) {
    __shared__ float sm[32];
    const int tid = threadIdx.x;
#pragma unroll
    for (int o = 16; o; o >>= 1) val += __shfl_down_sync(0xffffffffu, val, o);
    if ((tid & 31) == 0) sm[tid >> 5] = val;
    __syncthreads();
    if (tid < 32) {
        const int nw = (blockDim.x + 31) >> 5;
        float v = (tid < nw) ? sm[tid] : 0.f;
#pragma unroll
        for (int o = 4; o; o >>= 1) v += __shfl_down_sync(0xffffffffu, v, o);
        if (tid == 0) sm[0] = v;
    }
    __syncthreads();
    float r = sm[0];
    __syncthreads();
    return r;
}

// ============================================================================
// LN1 stats (warp-per-row, R13-verified) + FOLDED w2 transpose.
// Blocks [0, NM/8): stats. Blocks [NM/8, NM/8+512): transpose one 32x32 tile.
// ============================================================================
__global__ __launch_bounds__(256) void ln1_stats_kernel(const float* __restrict__ w2) {
    __shared__ float tile[32][33];
    if (blockIdx.x >= NM / 8) {
        const int t = blockIdx.x - NM / 8;          // 0..511
        const int h0 = (t & 31) * 32;
        const int d0 = (t >> 5) * 32;
        const int tx = threadIdx.x & 31;
        const int ty = threadIdx.x >> 5;            // 0..7
#pragma unroll
        for (int r = 0; r < 4; r++)
            tile[ty + r * 8][tx] = w2[(size_t)(d0 + ty + r * 8) * NH + h0 + tx];
        __syncthreads();
#pragma unroll
        for (int r = 0; r < 4; r++)
            g_w2t[(size_t)(h0 + ty + r * 8) * ND + d0 + tx] = tile[tx][ty + r * 8];
        return;
    }

    const int wid = threadIdx.x >> 5;               // 0..7
    const int lane = threadIdx.x & 31;
    const int row = blockIdx.x * 8 + wid;
    const float4* p = (const float4*)(g_h1 + (size_t)row * NH);

    float4 v[8];
#pragma unroll
    for (int j = 0; j < 8; j++) v[j] = p[lane + j * 32];

    float s = 0.f;
#pragma unroll
    for (int j = 0; j < 8; j++) s += (v[j].x + v[j].y) + (v[j].z + v[j].w);
#pragma unroll
    for (int o = 16; o; o >>= 1) s += __shfl_xor_sync(0xffffffffu, s, o);
    const float mean = s * (1.0f / NH);

    float sq = 0.f;
#pragma unroll
    for (int j = 0; j < 8; j++) {
        float d0 = v[j].x - mean, d1 = v[j].y - mean;
        float d2 = v[j].z - mean, d3 = v[j].w - mean;
        sq += (d0 * d0 + d1 * d1) + (d2 * d2 + d3 * d3);
    }
#pragma unroll
    for (int o = 16; o; o >>= 1) sq += __shfl_xor_sync(0xffffffffu, sq, o);
    const float inv = 1.0f / sqrtf(sq * (1.0f / NH) + 1e-5f);

    if (lane == 0) { g_mean[row] = mean; g_inv[row] = inv; }
}

// ============================================================================
// LIF layer 1 with inline LayerNorm, SOFTWARE-PIPELINED (R12-verified).
// ============================================================================
__global__ __launch_bounds__(128) void lif1_kernel(const float* __restrict__ g1,
                                                   const float* __restrict__ be1) {
    const int idx = blockIdx.x * 128 + threadIdx.x;   // NB*NH = 32768
    const int b = idx >> 10;
    const int h = idx & (NH - 1);
    const int tid = threadIdx.x;

    __shared__ float s_mean[NT];
    __shared__ float s_inv[NT];
#pragma unroll
    for (int t = tid; t < NT; t += 128) {
        s_mean[t] = g_mean[b * NT + t];
        s_inv[t]  = g_inv [b * NT + t];
    }
    __syncthreads();

    const float gh  = g1[h];
    const float beh = be1[h];
    const float* p = g_h1 + (size_t)b * NT * NH + h;
    unsigned char* q = g_s1 + (size_t)b * NT * NH + h;

    float xa[16], xb[16];
#pragma unroll
    for (int i = 0; i < 16; i++) xa[i] = p[(size_t)i * NH];

    float v = 0.f;
#pragma unroll 1
    for (int t0 = 0; t0 < NT; t0 += 32) {
#pragma unroll
        for (int i = 0; i < 16; i++) xb[i] = p[(size_t)(t0 + 16 + i) * NH];

        unsigned char sb[16];
#pragma unroll
        for (int i = 0; i < 16; i++) {
            float d = xa[i] - s_mean[t0 + i];
            float val = d * s_inv[t0 + i] * gh + beh;
            v = v + (val - v) * 0.5f;       // TAU = 2
            bool sp = (v >= 1.0f);          // V_TH = 1
            sb[i] = sp ? (unsigned char)1 : (unsigned char)0;
            v = sp ? 0.f : v;               // hard reset
        }
#pragma unroll
        for (int i = 0; i < 16; i++) q[(size_t)(t0 + i) * NH] = sb[i];

        if (t0 + 32 < NT) {
#pragma unroll
            for (int i = 0; i < 16; i++) xa[i] = p[(size_t)(t0 + 32 + i) * NH];
        }

#pragma unroll
        for (int i = 0; i < 16; i++) {
            float d = xb[i] - s_mean[t0 + 16 + i];
            float val = d * s_inv[t0 + 16 + i] * gh + beh;
            v = v + (val - v) * 0.5f;
            bool sp = (v >= 1.0f);
            sb[i] = sp ? (unsigned char)1 : (unsigned char)0;
            v = sp ? 0.f : v;
        }
#pragma unroll
        for (int i = 0; i < 16; i++) q[(size_t)(t0 + 16 + i) * NH] = sb[i];
    }
}

// ============================================================================
// fc2 (sparse gmem gather, L1-resident w2t) + fused LayerNorm2 (R4-verified).
// ncu R14: 59us, occ 94%, L1 82% -> L1-throughput bound; parked.
// ============================================================================
__global__ __launch_bounds__(128) void fc2ln2_kernel(const float* __restrict__ b2,
                                                     const float* __restrict__ g2,
                                                     const float* __restrict__ be2) {
    const int row = blockIdx.x;
    const int tid = threadIdx.x;
    const unsigned char* srow = g_s1 + (size_t)row * NH;

    ull m8 = ((const ull*)srow)[tid];           // 8 spike bytes
    int c = __popcll(m8);
    int pre = c;
#pragma unroll
    for (int o = 1; o < 32; o <<= 1) {
        int n = __shfl_up_sync(0xffffffffu, pre, o);
        if ((tid & 31) >= o) pre += n;
    }
    __shared__ int wsum[4];
    __shared__ unsigned short list[NH];
    __shared__ int s_total;
    if ((tid & 31) == 31) wsum[tid >> 5] = pre;
    __syncthreads();
    int base = 0;
#pragma unroll
    for (int w = 0; w < 4; w++)
        if (w < (tid >> 5)) base += wsum[w];
    int off = base + pre - c;
#pragma unroll
    for (int k = 0; k < 8; k++)
        if ((m8 >> (8 * k)) & 1ull) list[off++] = (unsigned short)(tid * 8 + k);
    if (tid == 127) s_total = base + pre;
    __syncthreads();

    const int cnt = s_total;
    const float* wbase = g_w2t + tid * 4;
    float4 acc = make_float4(0.f, 0.f, 0.f, 0.f);
    int i = 0;
    for (; i + 4 <= cnt; i += 4) {
        int h0 = list[i], h1 = list[i + 1], h2 = list[i + 2], h3 = list[i + 3];
        float4 w0 = *(const float4*)(wbase + (size_t)h0 * ND);
        float4 w1 = *(const float4*)(wbase + (size_t)h1 * ND);
        float4 w2v = *(const float4*)(wbase + (size_t)h2 * ND);
        float4 w3 = *(const float4*)(wbase + (size_t)h3 * ND);
        acc.x += w0.x; acc.y += w0.y; acc.z += w0.z; acc.w += w0.w;
        acc.x += w1.x; acc.y += w1.y; acc.z += w1.z; acc.w += w1.w;
        acc.x += w2v.x; acc.y += w2v.y; acc.z += w2v.z; acc.w += w2v.w;
        acc.x += w3.x; acc.y += w3.y; acc.z += w3.z; acc.w += w3.w;
    }
    for (; i < cnt; i++) {
        float4 w0 = *(const float4*)(wbase + (size_t)list[i] * ND);
        acc.x += w0.x; acc.y += w0.y; acc.z += w0.z; acc.w += w0.w;
    }
    float4 bb = ((const float4*)b2)[tid];
    acc.x += bb.x; acc.y += bb.y; acc.z += bb.z; acc.w += bb.w;

    // ---- fused LayerNorm2 ----
    float s = (acc.x + acc.y) + (acc.z + acc.w);
    float total = block_reduce_sum(s);
    float mean = total * (1.0f / ND);
    float d0 = acc.x - mean, d1 = acc.y - mean, d2 = acc.z - mean, d3 = acc.w - mean;
    float sq = (d0 * d0 + d1 * d1) + (d2 * d2 + d3 * d3);
    float tot2 = block_reduce_sum(sq);
    float inv = 1.0f / sqrtf(tot2 * (1.0f / ND) + 1e-5f);
    float4 gg = ((const float4*)g2)[tid];
    float4 bv = ((const float4*)be2)[tid];
    float4 o;
    o.x = d0 * inv * gg.x + bv.x;
    o.y = d1 * inv * gg.y + bv.y;
    o.z = d2 * inv * gg.z + bv.z;
    o.w = d3 * inv * gg.w + bv.w;
    ((float4*)(g_y + (size_t)row * ND))[tid] = o;
}

// ============================================================================
// LIF layer 2 + residual, SOFTWARE-PIPELINED (R11/R13-verified double buffer,
// rolled loop -> small code body; distance-1 prefetch).
// ============================================================================
__global__ __launch_bounds__(64) void lif2_kernel(const float* __restrict__ x,
                                                  float* __restrict__ out) {
    const int idx = blockIdx.x * 64 + threadIdx.x;    // NB*ND = 16384
    const int b = idx >> 9;
    const int d = idx & (ND - 1);
    const float* py = g_y + (size_t)b * NT * ND + d;
    const float* px = x + (size_t)b * NT * ND + d;
    float* po = out + (size_t)b * NT * ND + d;

    float ya[16], xa[16], yb[16], xb[16];
#pragma unroll
    for (int i = 0; i < 16; i++) { ya[i] = py[(size_t)i * ND]; }
#pragma unroll
    for (int i = 0; i < 16; i++) { xa[i] = px[(size_t)i * ND]; }

    float v = 0.f;
#pragma unroll 1
    for (int t0 = 0; t0 < NT; t0 += 32) {
#pragma unroll
        for (int i = 0; i < 16; i++) yb[i] = py[(size_t)(t0 + 16 + i) * ND];
#pragma unroll
        for (int i = 0; i < 16; i++) xb[i] = px[(size_t)(t0 + 16 + i) * ND];

        float ob[16];
#pragma unroll
        for (int i = 0; i < 16; i++) {
            v = v + (ya[i] - v) * 0.5f;
            bool sp = (v >= 1.0f);
            ob[i] = xa[i] + (sp ? 1.0f : 0.0f);
            v = sp ? 0.f : v;
        }
#pragma unroll
        for (int i = 0; i < 16; i++) po[(size_t)(t0 + i) * ND] = ob[i];

        if (t0 + 32 < NT) {
#pragma unroll
            for (int i = 0; i < 16; i++) ya[i] = py[(size_t)(t0 + 32 + i) * ND];
#pragma unroll
            for (int i = 0; i < 16; i++) xa[i] = px[(size_t)(t0 + 32 + i) * ND];
        }

#pragma unroll
        for (int i = 0; i < 16; i++) {
            v = v + (yb[i] - v) * 0.5f;
            bool sp = (v >= 1.0f);
            ob[i] = xb[i] + (sp ? 1.0f : 0.0f);
            v = sp ? 0.f : v;
        }
#pragma unroll
        for (int i = 0; i < 16; i++) po[(size_t)(t0 + 16 + i) * ND] = ob[i];
    }
}

// ============================================================================
extern "C" void kernel_launch(void* const* d_in, const int* in_sizes, int n_in,
                              void* d_out, int out_size) {
    const float* x   = (const float*)d_in[0];
    const float* w1  = (const float*)d_in[1];
    const float* b1  = (const float*)d_in[2];
    const float* g1  = (const float*)d_in[3];
    const float* be1 = (const float*)d_in[4];
    const float* w2  = (const float*)d_in[5];
    const float* b2  = (const float*)d_in[6];
    const float* g2  = (const float*)d_in[7];
    const float* be2 = (const float*)d_in[8];
    float* out = (float*)d_out;

    gemm1_kernel<<<dim3(NH / 128, NM / 128), 256>>>(x, w1, b1);
    ln1_stats_kernel<<<NM / 8 + 512, 256>>>(w2);   // stats + folded transpose
    lif1_kernel<<<(NB * NH) / 128, 128>>>(g1, be1);
    fc2ln2_kernel<<<NM, 128>>>(b2, g2, be2);
    lif2_kernel<<<(NB * ND) / 64, 64>>>(x, out);
}

// round 16
// speedup vs baseline: 1.0436x; 1.0170x over previous
#include <cuda_runtime.h>
#include <cstdint>

#define NB 32
#define NT 512
#define ND 512
#define NH 1024
#define NM (NB*NT)   // 16384 rows

typedef unsigned long long ull;

// ---- scratch (device globals; no runtime allocation allowed) ----
__device__ float         g_h1[(size_t)NM * NH];   // 64 MB fc1 raw output
__device__ unsigned char g_s1[(size_t)NM * NH];   // 16 MB spikes layer 1
__device__ float         g_y [(size_t)NM * ND];   // 32 MB fc2+ln2 out
__device__ float         g_w2t[(size_t)NH * ND];  //  2 MB w2 transposed to [H, D]
__device__ float         g_mean[NM];              // ln1 row means
__device__ float         g_inv [NM];              // ln1 row inv-std

// ---- packed fp32x2 helpers (Blackwell FFMA2, identical per-lane fp32 rounding) ----
__device__ __forceinline__ ull pack2(float lo, float hi) {
    ull r;
    asm("mov.b64 %0, {%1, %2};" : "=l"(r)
        : "r"(__float_as_uint(lo)), "r"(__float_as_uint(hi)));
    return r;
}
__device__ __forceinline__ void unpack2(ull v, float& lo, float& hi) {
    unsigned a, b;
    asm("mov.b64 {%0, %1}, %2;" : "=r"(a), "=r"(b) : "l"(v));
    lo = __uint_as_float(a); hi = __uint_as_float(b);
}
__device__ __forceinline__ ull fma2(ull a, ull b, ull c) {
    ull d;
    asm("fma.rn.f32x2 %0, %1, %2, %3;" : "=l"(d) : "l"(a), "l"(b), "l"(c));
    return d;
}

// ============================================================================
// GEMM1 (R12/R13-verified): g_h1[m,n] = sum_k x[m,k]*w1[n,k] + b1[n]
// ============================================================================
#define GEMM_STORE(BUF)                                                        \
    do {                                                                       \
        As[BUF][lk + 0][lm] = pa0.x; As[BUF][lk + 1][lm] = pa0.y;              \
        As[BUF][lk + 2][lm] = pa0.z; As[BUF][lk + 3][lm] = pa0.w;              \
        As[BUF][lk + 0][lm + 64] = pa1.x; As[BUF][lk + 1][lm + 64] = pa1.y;    \
        As[BUF][lk + 2][lm + 64] = pa1.z; As[BUF][lk + 3][lm + 64] = pa1.w;    \
        Bs[BUF][lk + 0][lm] = pb0.x; Bs[BUF][lk + 1][lm] = pb0.y;              \
        Bs[BUF][lk + 2][lm] = pb0.z; Bs[BUF][lk + 3][lm] = pb0.w;              \
        Bs[BUF][lk + 0][lm + 64] = pb1.x; Bs[BUF][lk + 1][lm + 64] = pb1.y;    \
        Bs[BUF][lk + 2][lm + 64] = pb1.z; Bs[BUF][lk + 3][lm + 64] = pb1.w;    \
    } while (0)

#define GEMM_LOAD(KT)                                                          \
    do {                                                                       \
        const float* Ap2 = Ap + (KT) * 16;                                     \
        const float* Bp2 = Bp + (KT) * 16;                                     \
        pa0 = *(const float4*)(Ap2);                                           \
        pa1 = *(const float4*)(Ap2 + (size_t)64 * ND);                         \
        pb0 = *(const float4*)(Bp2);                                           \
        pb1 = *(const float4*)(Bp2 + (size_t)64 * ND);                         \
    } while (0)

#define GEMM_COMPUTE(BUF)                                                      \
    _Pragma("unroll")                                                          \
    for (int kk = 0; kk < 16; kk++) {                                          \
        float4 a0 = *(const float4*)&As[BUF][kk][ty * 8];                      \
        float4 a1 = *(const float4*)&As[BUF][kk][ty * 8 + 4];                  \
        ulonglong2 bl0 = *(const ulonglong2*)&Bs[BUF][kk][tx * 8];             \
        ulonglong2 bl1 = *(const ulonglong2*)&Bs[BUF][kk][tx * 8 + 4];         \
        float av[8] = {a0.x, a0.y, a0.z, a0.w, a1.x, a1.y, a1.z, a1.w};        \
        _Pragma("unroll")                                                      \
        for (int i = 0; i < 8; i++) {                                          \
            ull aa = pack2(av[i], av[i]);                                      \
            acc[i][0] = fma2(aa, bl0.x, acc[i][0]);                            \
            acc[i][1] = fma2(aa, bl0.y, acc[i][1]);                            \
            acc[i][2] = fma2(aa, bl1.x, acc[i][2]);                            \
            acc[i][3] = fma2(aa, bl1.y, acc[i][3]);                            \
        }                                                                      \
    }

__global__ __launch_bounds__(256, 2) void gemm1_kernel(const float* __restrict__ A,
                                                       const float* __restrict__ W,
                                                       const float* __restrict__ bias) {
    __shared__ __align__(16) float As[2][16][132];
    __shared__ __align__(16) float Bs[2][16][132];
    const int tid  = threadIdx.x;
    const int row0 = blockIdx.y * 128;
    const int col0 = blockIdx.x * 128;
    const int tx = tid & 15;
    const int ty = tid >> 4;
    const int lm = tid >> 2;
    const int lk = (tid & 3) * 4;

    const float* Ap = A + (size_t)(row0 + lm) * ND + lk;
    const float* Bp = W + (size_t)(col0 + lm) * ND + lk;

    ull acc[8][4];
#pragma unroll
    for (int i = 0; i < 8; i++)
#pragma unroll
        for (int j = 0; j < 4; j++) acc[i][j] = 0ull;

    float4 pa0, pa1, pb0, pb1;
    GEMM_LOAD(0);
    GEMM_STORE(0);
    GEMM_LOAD(1);
    __syncthreads();

#pragma unroll 1
    for (int kt = 0; kt < 32; kt += 2) {
        GEMM_STORE(1);
        if (kt + 2 < 32) GEMM_LOAD(kt + 2);
        GEMM_COMPUTE(0);
        __syncthreads();
        if (kt + 2 < 32) {
            GEMM_STORE(0);
            if (kt + 3 < 32) GEMM_LOAD(kt + 3);
        }
        GEMM_COMPUTE(1);
        __syncthreads();
    }

    float bv[8];
#pragma unroll
    for (int j = 0; j < 8; j++) bv[j] = bias[col0 + tx * 8 + j];
#pragma unroll
    for (int i = 0; i < 8; i++) {
        float o[8];
        unpack2(acc[i][0], o[0], o[1]);
        unpack2(acc[i][1], o[2], o[3]);
        unpack2(acc[i][2], o[4], o[5]);
        unpack2(acc[i][3], o[6], o[7]);
#pragma unroll
        for (int j = 0; j < 8; j++) o[j] += bv[j];
        float* cp = g_h1 + (size_t)(row0 + ty * 8 + i) * NH + col0 + tx * 8;
        ((float4*)cp)[0] = make_float4(o[0], o[1], o[2], o[3]);
        ((float4*)cp)[1] = make_float4(o[4], o[5], o[6], o[7]);
    }
}

// ============================================================================
// block-wide reduction (blockDim multiple of 32, <= 256)
// ============================================================================
__device__ __forceinline__ float block_reduce_sum(float val) {
    __shared__ float sm[32];
    const int tid = threadIdx.x;
#pragma unroll
    for (int o = 16; o; o >>= 1) val += __shfl_down_sync(0xffffffffu, val, o);
    if ((tid & 31) == 0) sm[tid >> 5] = val;
    __syncthreads();
    if (tid < 32) {
        const int nw = (blockDim.x + 31) >> 5;
        float v = (tid < nw) ? sm[tid] : 0.f;
#pragma unroll
        for (int o = 4; o; o >>= 1) v += __shfl_down_sync(0xffffffffu, v, o);
        if (tid == 0) sm[0] = v;
    }
    __syncthreads();
    float r = sm[0];
    __syncthreads();
    return r;
}

// ============================================================================
// LN1 stats (warp-per-row, R13-verified) + FOLDED w2 transpose.
// ============================================================================
__global__ __launch_bounds__(256) void ln1_stats_kernel(const float* __restrict__ w2) {
    __shared__ float tile[32][33];
    if (blockIdx.x >= NM / 8) {
        const int t = blockIdx.x - NM / 8;          // 0..511
        const int h0 = (t & 31) * 32;
        const int d0 = (t >> 5) * 32;
        const int tx = threadIdx.x & 31;
        const int ty = threadIdx.x >> 5;            // 0..7
#pragma unroll
        for (int r = 0; r < 4; r++)
            tile[ty + r * 8][tx] = w2[(size_t)(d0 + ty + r * 8) * NH + h0 + tx];
        __syncthreads();
#pragma unroll
        for (int r = 0; r < 4; r++)
            g_w2t[(size_t)(h0 + ty + r * 8) * ND + d0 + tx] = tile[tx][ty + r * 8];
        return;
    }

    const int wid = threadIdx.x >> 5;               // 0..7
    const int lane = threadIdx.x & 31;
    const int row = blockIdx.x * 8 + wid;
    const float4* p = (const float4*)(g_h1 + (size_t)row * NH);

    float4 v[8];
#pragma unroll
    for (int j = 0; j < 8; j++) v[j] = p[lane + j * 32];

    float s = 0.f;
#pragma unroll
    for (int j = 0; j < 8; j++) s += (v[j].x + v[j].y) + (v[j].z + v[j].w);
#pragma unroll
    for (int o = 16; o; o >>= 1) s += __shfl_xor_sync(0xffffffffu, s, o);
    const float mean = s * (1.0f / NH);

    float sq = 0.f;
#pragma unroll
    for (int j = 0; j < 8; j++) {
        float d0 = v[j].x - mean, d1 = v[j].y - mean;
        float d2 = v[j].z - mean, d3 = v[j].w - mean;
        sq += (d0 * d0 + d1 * d1) + (d2 * d2 + d3 * d3);
    }
#pragma unroll
    for (int o = 16; o; o >>= 1) sq += __shfl_xor_sync(0xffffffffu, sq, o);
    const float inv = 1.0f / sqrtf(sq * (1.0f / NH) + 1e-5f);

    if (lane == 0) { g_mean[row] = mean; g_inv[row] = inv; }
}

// ============================================================================
// LIF layer 1 with inline LayerNorm, SOFTWARE-PIPELINED (R12-verified).
// ============================================================================
__global__ __launch_bounds__(128) void lif1_kernel(const float* __restrict__ g1,
                                                   const float* __restrict__ be1) {
    const int idx = blockIdx.x * 128 + threadIdx.x;   // NB*NH = 32768
    const int b = idx >> 10;
    const int h = idx & (NH - 1);
    const int tid = threadIdx.x;

    __shared__ float s_mean[NT];
    __shared__ float s_inv[NT];
#pragma unroll
    for (int t = tid; t < NT; t += 128) {
        s_mean[t] = g_mean[b * NT + t];
        s_inv[t]  = g_inv [b * NT + t];
    }
    __syncthreads();

    const float gh  = g1[h];
    const float beh = be1[h];
    const float* p = g_h1 + (size_t)b * NT * NH + h;
    unsigned char* q = g_s1 + (size_t)b * NT * NH + h;

    float xa[16], xb[16];
#pragma unroll
    for (int i = 0; i < 16; i++) xa[i] = p[(size_t)i * NH];

    float v = 0.f;
#pragma unroll 1
    for (int t0 = 0; t0 < NT; t0 += 32) {
#pragma unroll
        for (int i = 0; i < 16; i++) xb[i] = p[(size_t)(t0 + 16 + i) * NH];

        unsigned char sb[16];
#pragma unroll
        for (int i = 0; i < 16; i++) {
            float d = xa[i] - s_mean[t0 + i];
            float val = d * s_inv[t0 + i] * gh + beh;
            v = v + (val - v) * 0.5f;       // TAU = 2
            bool sp = (v >= 1.0f);          // V_TH = 1
            sb[i] = sp ? (unsigned char)1 : (unsigned char)0;
            v = sp ? 0.f : v;               // hard reset
        }
#pragma unroll
        for (int i = 0; i < 16; i++) q[(size_t)(t0 + i) * NH] = sb[i];

        if (t0 + 32 < NT) {
#pragma unroll
            for (int i = 0; i < 16; i++) xa[i] = p[(size_t)(t0 + 32 + i) * NH];
        }

#pragma unroll
        for (int i = 0; i < 16; i++) {
            float d = xb[i] - s_mean[t0 + 16 + i];
            float val = d * s_inv[t0 + 16 + i] * gh + beh;
            v = v + (val - v) * 0.5f;
            bool sp = (v >= 1.0f);
            sb[i] = sp ? (unsigned char)1 : (unsigned char)0;
            v = sp ? 0.f : v;
        }
#pragma unroll
        for (int i = 0; i < 16; i++) q[(size_t)(t0 + 16 + i) * NH] = sb[i];
    }
}

// ============================================================================
// fc2 (sparse gmem gather, L1-resident w2t) + fused LayerNorm2 (R4-verified).
// ncu: 59us, occ 94%, L1 83% -> L1-throughput bound; parked.
// ============================================================================
__global__ __launch_bounds__(128) void fc2ln2_kernel(const float* __restrict__ b2,
                                                     const float* __restrict__ g2,
                                                     const float* __restrict__ be2) {
    const int row = blockIdx.x;
    const int tid = threadIdx.x;
    const unsigned char* srow = g_s1 + (size_t)row * NH;

    ull m8 = ((const ull*)srow)[tid];           // 8 spike bytes
    int c = __popcll(m8);
    int pre = c;
#pragma unroll
    for (int o = 1; o < 32; o <<= 1) {
        int n = __shfl_up_sync(0xffffffffu, pre, o);
        if ((tid & 31) >= o) pre += n;
    }
    __shared__ int wsum[4];
    __shared__ unsigned short list[NH];
    __shared__ int s_total;
    if ((tid & 31) == 31) wsum[tid >> 5] = pre;
    __syncthreads();
    int base = 0;
#pragma unroll
    for (int w = 0; w < 4; w++)
        if (w < (tid >> 5)) base += wsum[w];
    int off = base + pre - c;
#pragma unroll
    for (int k = 0; k < 8; k++)
        if ((m8 >> (8 * k)) & 1ull) list[off++] = (unsigned short)(tid * 8 + k);
    if (tid == 127) s_total = base + pre;
    __syncthreads();

    const int cnt = s_total;
    const float* wbase = g_w2t + tid * 4;
    float4 acc = make_float4(0.f, 0.f, 0.f, 0.f);
    int i = 0;
    for (; i + 4 <= cnt; i += 4) {
        int h0 = list[i], h1 = list[i + 1], h2 = list[i + 2], h3 = list[i + 3];
        float4 w0 = *(const float4*)(wbase + (size_t)h0 * ND);
        float4 w1 = *(const float4*)(wbase + (size_t)h1 * ND);
        float4 w2v = *(const float4*)(wbase + (size_t)h2 * ND);
        float4 w3 = *(const float4*)(wbase + (size_t)h3 * ND);
        acc.x += w0.x; acc.y += w0.y; acc.z += w0.z; acc.w += w0.w;
        acc.x += w1.x; acc.y += w1.y; acc.z += w1.z; acc.w += w1.w;
        acc.x += w2v.x; acc.y += w2v.y; acc.z += w2v.z; acc.w += w2v.w;
        acc.x += w3.x; acc.y += w3.y; acc.z += w3.z; acc.w += w3.w;
    }
    for (; i < cnt; i++) {
        float4 w0 = *(const float4*)(wbase + (size_t)list[i] * ND);
        acc.x += w0.x; acc.y += w0.y; acc.z += w0.z; acc.w += w0.w;
    }
    float4 bb = ((const float4*)b2)[tid];
    acc.x += bb.x; acc.y += bb.y; acc.z += bb.z; acc.w += bb.w;

    // ---- fused LayerNorm2 ----
    float s = (acc.x + acc.y) + (acc.z + acc.w);
    float total = block_reduce_sum(s);
    float mean = total * (1.0f / ND);
    float d0 = acc.x - mean, d1 = acc.y - mean, d2 = acc.z - mean, d3 = acc.w - mean;
    float sq = (d0 * d0 + d1 * d1) + (d2 * d2 + d3 * d3);
    float tot2 = block_reduce_sum(sq);
    float inv = 1.0f / sqrtf(tot2 * (1.0f / ND) + 1e-5f);
    float4 gg = ((const float4*)g2)[tid];
    float4 bv = ((const float4*)be2)[tid];
    float4 o;
    o.x = d0 * inv * gg.x + bv.x;
    o.y = d1 * inv * gg.y + bv.y;
    o.z = d2 * inv * gg.z + bv.z;
    o.w = d3 * inv * gg.w + bv.w;
    ((float4*)(g_y + (size_t)row * ND))[tid] = o;
}

// ============================================================================
// LIF layer 2 + residual, prefetch DISTANCE-2 pipeline: 4 register buffers,
// outer loop unrolled by exactly 4 chunks -> compile-time buffer roles,
// ~4KB body (I$-safe). Per-element arithmetic identical -> bitwise-exact.
// ============================================================================
#define L2_PREFETCH(BUF, CH)                                                   \
    do {                                                                       \
        if ((CH) < 32) {                                                       \
            _Pragma("unroll")                                                  \
            for (int i = 0; i < 16; i++)                                       \
                yb[BUF][i] = py[(size_t)((CH) * 16 + i) * ND];                 \
            _Pragma("unroll")                                                  \
            for (int i = 0; i < 16; i++)                                       \
                xb[BUF][i] = px[(size_t)((CH) * 16 + i) * ND];                 \
        }                                                                      \
    } while (0)

#define L2_COMPUTE(BUF, CH)                                                    \
    do {                                                                       \
        float ob[16];                                                          \
        _Pragma("unroll")                                                      \
        for (int i = 0; i < 16; i++) {                                         \
            v = v + (yb[BUF][i] - v) * 0.5f;                                   \
            bool sp = (v >= 1.0f);                                             \
            ob[i] = xb[BUF][i] + (sp ? 1.0f : 0.0f);                           \
            v = sp ? 0.f : v;                                                  \
        }                                                                      \
        _Pragma("unroll")                                                      \
        for (int i = 0; i < 16; i++)                                           \
            po[(size_t)((CH) * 16 + i) * ND] = ob[i];                          \
    } while (0)

__global__ __launch_bounds__(64) void lif2_kernel(const float* __restrict__ x,
                                                  float* __restrict__ out) {
    const int idx = blockIdx.x * 64 + threadIdx.x;    // NB*ND = 16384
    const int b = idx >> 9;
    const int d = idx & (ND - 1);
    const float* py = g_y + (size_t)b * NT * ND + d;
    const float* px = x + (size_t)b * NT * ND + d;
    float* po = out + (size_t)b * NT * ND + d;

    float yb[4][16], xb[4][16];
    L2_PREFETCH(0, 0);
    L2_PREFETCH(1, 1);

    float v = 0.f;
#pragma unroll 1
    for (int c = 0; c < 32; c += 4) {       // 8 iterations, 4 chunks each
        L2_PREFETCH(2, c + 2);
        L2_COMPUTE(0, c);
        L2_PREFETCH(3, c + 3);
        L2_COMPUTE(1, c + 1);
        L2_PREFETCH(0, c + 4);
        L2_COMPUTE(2, c + 2);
        L2_PREFETCH(1, c + 5);
        L2_COMPUTE(3, c + 3);
    }
}

// ============================================================================
extern "C" void kernel_launch(void* const* d_in, const int* in_sizes, int n_in,
                              void* d_out, int out_size) {
    const float* x   = (const float*)d_in[0];
    const float* w1  = (const float*)d_in[1];
    const float* b1  = (const float*)d_in[2];
    const float* g1  = (const float*)d_in[3];
    const float* be1 = (const float*)d_in[4];
    const float* w2  = (const float*)d_in[5];
    const float* b2  = (const float*)d_in[6];
    const float* g2  = (const float*)d_in[7];
    const float* be2 = (const float*)d_in[8];
    float* out = (float*)d_out;

    gemm1_kernel<<<dim3(NH / 128, NM / 128), 256>>>(x, w1, b1);
    ln1_stats_kernel<<<NM / 8 + 512, 256>>>(w2);   // stats + folded transpose
    lif1_kernel<<<(NB * NH) / 128, 128>>>(g1, be1);
    fc2ln2_kernel<<<NM, 128>>>(b2, g2, be2);
    lif2_kernel<<<(NB * ND) / 64, 64>>>(x, out);
}

// round 17
// speedup vs baseline: 1.0449x; 1.0013x over previous
#include <cuda_runtime.h>
#include <cstdint>

#define NB 32
#define NT 512
#define ND 512
#define NH 1024
#define NM (NB*NT)   // 16384 rows

typedef unsigned long long ull;

// ---- scratch (device globals; no runtime allocation allowed) ----
__device__ float         g_h1[(size_t)NM * NH];   // 64 MB fc1 raw output
__device__ unsigned char g_s1[(size_t)NM * NH];   // 16 MB spikes layer 1
__device__ float         g_y [(size_t)NM * ND];   // 32 MB fc2+ln2 out
__device__ float         g_w2t[(size_t)NH * ND];  //  2 MB w2 transposed to [H, D]
__device__ float         g_mean[NM];              // ln1 row means
__device__ float         g_inv [NM];              // ln1 row inv-std

// ---- packed fp32x2 helpers (Blackwell FFMA2, identical per-lane fp32 rounding) ----
__device__ __forceinline__ ull pack2(float lo, float hi) {
    ull r;
    asm("mov.b64 %0, {%1, %2};" : "=l"(r)
        : "r"(__float_as_uint(lo)), "r"(__float_as_uint(hi)));
    return r;
}
__device__ __forceinline__ void unpack2(ull v, float& lo, float& hi) {
    unsigned a, b;
    asm("mov.b64 {%0, %1}, %2;" : "=r"(a), "=r"(b) : "l"(v));
    lo = __uint_as_float(a); hi = __uint_as_float(b);
}
__device__ __forceinline__ ull fma2(ull a, ull b, ull c) {
    ull d;
    asm("fma.rn.f32x2 %0, %1, %2, %3;" : "=l"(d) : "l"(a), "l"(b), "l"(c));
    return d;
}

// ============================================================================
// GEMM1 (R12/R13-verified): g_h1[m,n] = sum_k x[m,k]*w1[n,k] + b1[n]
// ============================================================================
#define GEMM_STORE(BUF)                                                        \
    do {                                                                       \
        As[BUF][lk + 0][lm] = pa0.x; As[BUF][lk + 1][lm] = pa0.y;              \
        As[BUF][lk + 2][lm] = pa0.z; As[BUF][lk + 3][lm] = pa0.w;              \
        As[BUF][lk + 0][lm + 64] = pa1.x; As[BUF][lk + 1][lm + 64] = pa1.y;    \
        As[BUF][lk + 2][lm + 64] = pa1.z; As[BUF][lk + 3][lm + 64] = pa1.w;    \
        Bs[BUF][lk + 0][lm] = pb0.x; Bs[BUF][lk + 1][lm] = pb0.y;              \
        Bs[BUF][lk + 2][lm] = pb0.z; Bs[BUF][lk + 3][lm] = pb0.w;              \
        Bs[BUF][lk + 0][lm + 64] = pb1.x; Bs[BUF][lk + 1][lm + 64] = pb1.y;    \
        Bs[BUF][lk + 2][lm + 64] = pb1.z; Bs[BUF][lk + 3][lm + 64] = pb1.w;    \
    } while (0)

#define GEMM_LOAD(KT)                                                          \
    do {                                                                       \
        const float* Ap2 = Ap + (KT) * 16;                                     \
        const float* Bp2 = Bp + (KT) * 16;                                     \
        pa0 = *(const float4*)(Ap2);                                           \
        pa1 = *(const float4*)(Ap2 + (size_t)64 * ND);                         \
        pb0 = *(const float4*)(Bp2);                                           \
        pb1 = *(const float4*)(Bp2 + (size_t)64 * ND);                         \
    } while (0)

#define GEMM_COMPUTE(BUF)                                                      \
    _Pragma("unroll")                                                          \
    for (int kk = 0; kk < 16; kk++) {                                          \
        float4 a0 = *(const float4*)&As[BUF][kk][ty * 8];                      \
        float4 a1 = *(const float4*)&As[BUF][kk][ty * 8 + 4];                  \
        ulonglong2 bl0 = *(const ulonglong2*)&Bs[BUF][kk][tx * 8];             \
        ulonglong2 bl1 = *(const ulonglong2*)&Bs[BUF][kk][tx * 8 + 4];         \
        float av[8] = {a0.x, a0.y, a0.z, a0.w, a1.x, a1.y, a1.z, a1.w};        \
        _Pragma("unroll")                                                      \
        for (int i = 0; i < 8; i++) {                                          \
            ull aa = pack2(av[i], av[i]);                                      \
            acc[i][0] = fma2(aa, bl0.x, acc[i][0]);                            \
            acc[i][1] = fma2(aa, bl0.y, acc[i][1]);                            \
            acc[i][2] = fma2(aa, bl1.x, acc[i][2]);                            \
            acc[i][3] = fma2(aa, bl1.y, acc[i][3]);                            \
        }                                                                      \
    }

__global__ __launch_bounds__(256, 2) void gemm1_kernel(const float* __restrict__ A,
                                                       const float* __restrict__ W,
                                                       const float* __restrict__ bias) {
    __shared__ __align__(16) float As[2][16][132];
    __shared__ __align__(16) float Bs[2][16][132];
    const int tid  = threadIdx.x;
    const int row0 = blockIdx.y * 128;
    const int col0 = blockIdx.x * 128;
    const int tx = tid & 15;
    const int ty = tid >> 4;
    const int lm = tid >> 2;
    const int lk = (tid & 3) * 4;

    const float* Ap = A + (size_t)(row0 + lm) * ND + lk;
    const float* Bp = W + (size_t)(col0 + lm) * ND + lk;

    ull acc[8][4];
#pragma unroll
    for (int i = 0; i < 8; i++)
#pragma unroll
        for (int j = 0; j < 4; j++) acc[i][j] = 0ull;

    float4 pa0, pa1, pb0, pb1;
    GEMM_LOAD(0);
    GEMM_STORE(0);
    GEMM_LOAD(1);
    __syncthreads();

#pragma unroll 1
    for (int kt = 0; kt < 32; kt += 2) {
        GEMM_STORE(1);
        if (kt + 2 < 32) GEMM_LOAD(kt + 2);
        GEMM_COMPUTE(0);
        __syncthreads();
        if (kt + 2 < 32) {
            GEMM_STORE(0);
            if (kt + 3 < 32) GEMM_LOAD(kt + 3);
        }
        GEMM_COMPUTE(1);
        __syncthreads();
    }

    float bv[8];
#pragma unroll
    for (int j = 0; j < 8; j++) bv[j] = bias[col0 + tx * 8 + j];
#pragma unroll
    for (int i = 0; i < 8; i++) {
        float o[8];
        unpack2(acc[i][0], o[0], o[1]);
        unpack2(acc[i][1], o[2], o[3]);
        unpack2(acc[i][2], o[4], o[5]);
        unpack2(acc[i][3], o[6], o[7]);
#pragma unroll
        for (int j = 0; j < 8; j++) o[j] += bv[j];
        float* cp = g_h1 + (size_t)(row0 + ty * 8 + i) * NH + col0 + tx * 8;
        ((float4*)cp)[0] = make_float4(o[0], o[1], o[2], o[3]);
        ((float4*)cp)[1] = make_float4(o[4], o[5], o[6], o[7]);
    }
}

// ============================================================================
// block-wide reduction (blockDim multiple of 32, <= 256)
// ============================================================================
__device__ __forceinline__ float block_reduce_sum(float val) {
    __shared__ float sm[32];
    const int tid = threadIdx.x;
#pragma unroll
    for (int o = 16; o; o >>= 1) val += __shfl_down_sync(0xffffffffu, val, o);
    if ((tid & 31) == 0) sm[tid >> 5] = val;
    __syncthreads();
    if (tid < 32) {
        const int nw = (blockDim.x + 31) >> 5;
        float v = (tid < nw) ? sm[tid] : 0.f;
#pragma unroll
        for (int o = 4; o; o >>= 1) v += __shfl_down_sync(0xffffffffu, v, o);
        if (tid == 0) sm[0] = v;
    }
    __syncthreads();
    float r = sm[0];
    __syncthreads();
    return r;
}

// ============================================================================
// LN1 stats (warp-per-row, R13-verified) + FOLDED w2 transpose.
// ============================================================================
__global__ __launch_bounds__(256) void ln1_stats_kernel(const float* __restrict__ w2) {
    __shared__ float tile[32][33];
    if (blockIdx.x >= NM / 8) {
        const int t = blockIdx.x - NM / 8;          // 0..511
        const int h0 = (t & 31) * 32;
        const int d0 = (t >> 5) * 32;
        const int tx = threadIdx.x & 31;
        const int ty = threadIdx.x >> 5;            // 0..7
#pragma unroll
        for (int r = 0; r < 4; r++)
            tile[ty + r * 8][tx] = w2[(size_t)(d0 + ty + r * 8) * NH + h0 + tx];
        __syncthreads();
#pragma unroll
        for (int r = 0; r < 4; r++)
            g_w2t[(size_t)(h0 + ty + r * 8) * ND + d0 + tx] = tile[tx][ty + r * 8];
        return;
    }

    const int wid = threadIdx.x >> 5;               // 0..7
    const int lane = threadIdx.x & 31;
    const int row = blockIdx.x * 8 + wid;
    const float4* p = (const float4*)(g_h1 + (size_t)row * NH);

    float4 v[8];
#pragma unroll
    for (int j = 0; j < 8; j++) v[j] = p[lane + j * 32];

    float s = 0.f;
#pragma unroll
    for (int j = 0; j < 8; j++) s += (v[j].x + v[j].y) + (v[j].z + v[j].w);
#pragma unroll
    for (int o = 16; o; o >>= 1) s += __shfl_xor_sync(0xffffffffu, s, o);
    const float mean = s * (1.0f / NH);

    float sq = 0.f;
#pragma unroll
    for (int j = 0; j < 8; j++) {
        float d0 = v[j].x - mean, d1 = v[j].y - mean;
        float d2 = v[j].z - mean, d3 = v[j].w - mean;
        sq += (d0 * d0 + d1 * d1) + (d2 * d2 + d3 * d3);
    }
#pragma unroll
    for (int o = 16; o; o >>= 1) sq += __shfl_xor_sync(0xffffffffu, sq, o);
    const float inv = 1.0f / sqrtf(sq * (1.0f / NH) + 1e-5f);

    if (lane == 0) { g_mean[row] = mean; g_inv[row] = inv; }
}

// ============================================================================
// LIF layer 1 with inline LayerNorm, prefetch DISTANCE-2 pipeline:
// 4 register buffers, loop unrolled by exactly 4 chunks (compile-time roles,
// I$-safe body). Per-element arithmetic identical -> bitwise-exact.
// ============================================================================
#define L1_PREFETCH(BUF, CH)                                                   \
    do {                                                                       \
        if ((CH) < 32) {                                                       \
            _Pragma("unroll")                                                  \
            for (int i = 0; i < 16; i++)                                       \
                xbuf[BUF][i] = p[(size_t)((CH) * 16 + i) * NH];                \
        }                                                                      \
    } while (0)

#define L1_COMPUTE(BUF, CH)                                                    \
    do {                                                                       \
        unsigned char sb[16];                                                  \
        _Pragma("unroll")                                                      \
        for (int i = 0; i < 16; i++) {                                         \
            float dd = xbuf[BUF][i] - s_mean[(CH) * 16 + i];                   \
            float val = dd * s_inv[(CH) * 16 + i] * gh + beh;                  \
            v = v + (val - v) * 0.5f;                                          \
            bool sp = (v >= 1.0f);                                             \
            sb[i] = sp ? (unsigned char)1 : (unsigned char)0;                  \
            v = sp ? 0.f : v;                                                  \
        }                                                                      \
        _Pragma("unroll")                                                      \
        for (int i = 0; i < 16; i++)                                           \
            q[(size_t)((CH) * 16 + i) * NH] = sb[i];                           \
    } while (0)

__global__ __launch_bounds__(128) void lif1_kernel(const float* __restrict__ g1,
                                                   const float* __restrict__ be1) {
    const int idx = blockIdx.x * 128 + threadIdx.x;   // NB*NH = 32768
    const int b = idx >> 10;
    const int h = idx & (NH - 1);
    const int tid = threadIdx.x;

    __shared__ float s_mean[NT];
    __shared__ float s_inv[NT];
#pragma unroll
    for (int t = tid; t < NT; t += 128) {
        s_mean[t] = g_mean[b * NT + t];
        s_inv[t]  = g_inv [b * NT + t];
    }
    __syncthreads();

    const float gh  = g1[h];
    const float beh = be1[h];
    const float* p = g_h1 + (size_t)b * NT * NH + h;
    unsigned char* q = g_s1 + (size_t)b * NT * NH + h;

    float xbuf[4][16];
    L1_PREFETCH(0, 0);
    L1_PREFETCH(1, 1);

    float v = 0.f;
#pragma unroll 1
    for (int c = 0; c < 32; c += 4) {       // 8 iterations, 4 chunks each
        L1_PREFETCH(2, c + 2);
        L1_COMPUTE(0, c);
        L1_PREFETCH(3, c + 3);
        L1_COMPUTE(1, c + 1);
        L1_PREFETCH(0, c + 4);
        L1_COMPUTE(2, c + 2);
        L1_PREFETCH(1, c + 5);
        L1_COMPUTE(3, c + 3);
    }
}

// ============================================================================
// fc2 (sparse gmem gather, L1-resident w2t) + fused LayerNorm2 (R4-verified).
// ncu: 59us, occ 94%, L1 83% -> L1-throughput bound; parked.
// ============================================================================
__global__ __launch_bounds__(128) void fc2ln2_kernel(const float* __restrict__ b2,
                                                     const float* __restrict__ g2,
                                                     const float* __restrict__ be2) {
    const int row = blockIdx.x;
    const int tid = threadIdx.x;
    const unsigned char* srow = g_s1 + (size_t)row * NH;

    ull m8 = ((const ull*)srow)[tid];           // 8 spike bytes
    int c = __popcll(m8);
    int pre = c;
#pragma unroll
    for (int o = 1; o < 32; o <<= 1) {
        int n = __shfl_up_sync(0xffffffffu, pre, o);
        if ((tid & 31) >= o) pre += n;
    }
    __shared__ int wsum[4];
    __shared__ unsigned short list[NH];
    __shared__ int s_total;
    if ((tid & 31) == 31) wsum[tid >> 5] = pre;
    __syncthreads();
    int base = 0;
#pragma unroll
    for (int w = 0; w < 4; w++)
        if (w < (tid >> 5)) base += wsum[w];
    int off = base + pre - c;
#pragma unroll
    for (int k = 0; k < 8; k++)
        if ((m8 >> (8 * k)) & 1ull) list[off++] = (unsigned short)(tid * 8 + k);
    if (tid == 127) s_total = base + pre;
    __syncthreads();

    const int cnt = s_total;
    const float* wbase = g_w2t + tid * 4;
    float4 acc = make_float4(0.f, 0.f, 0.f, 0.f);
    int i = 0;
    for (; i + 4 <= cnt; i += 4) {
        int h0 = list[i], h1 = list[i + 1], h2 = list[i + 2], h3 = list[i + 3];
        float4 w0 = *(const float4*)(wbase + (size_t)h0 * ND);
        float4 w1 = *(const float4*)(wbase + (size_t)h1 * ND);
        float4 w2v = *(const float4*)(wbase + (size_t)h2 * ND);
        float4 w3 = *(const float4*)(wbase + (size_t)h3 * ND);
        acc.x += w0.x; acc.y += w0.y; acc.z += w0.z; acc.w += w0.w;
        acc.x += w1.x; acc.y += w1.y; acc.z += w1.z; acc.w += w1.w;
        acc.x += w2v.x; acc.y += w2v.y; acc.z += w2v.z; acc.w += w2v.w;
        acc.x += w3.x; acc.y += w3.y; acc.z += w3.z; acc.w += w3.w;
    }
    for (; i < cnt; i++) {
        float4 w0 = *(const float4*)(wbase + (size_t)list[i] * ND);
        acc.x += w0.x; acc.y += w0.y; acc.z += w0.z; acc.w += w0.w;
    }
    float4 bb = ((const float4*)b2)[tid];
    acc.x += bb.x; acc.y += bb.y; acc.z += bb.z; acc.w += bb.w;

    // ---- fused LayerNorm2 ----
    float s = (acc.x + acc.y) + (acc.z + acc.w);
    float total = block_reduce_sum(s);
    float mean = total * (1.0f / ND);
    float d0 = acc.x - mean, d1 = acc.y - mean, d2 = acc.z - mean, d3 = acc.w - mean;
    float sq = (d0 * d0 + d1 * d1) + (d2 * d2 + d3 * d3);
    float tot2 = block_reduce_sum(sq);
    float inv = 1.0f / sqrtf(tot2 * (1.0f / ND) + 1e-5f);
    float4 gg = ((const float4*)g2)[tid];
    float4 bv = ((const float4*)be2)[tid];
    float4 o;
    o.x = d0 * inv * gg.x + bv.x;
    o.y = d1 * inv * gg.y + bv.y;
    o.z = d2 * inv * gg.z + bv.z;
    o.w = d3 * inv * gg.w + bv.w;
    ((float4*)(g_y + (size_t)row * ND))[tid] = o;
}

// ============================================================================
// LIF layer 2 + residual, prefetch DISTANCE-2 pipeline (R16-verified).
// ============================================================================
#define L2_PREFETCH(BUF, CH)                                                   \
    do {                                                                       \
        if ((CH) < 32) {                                                       \
            _Pragma("unroll")                                                  \
            for (int i = 0; i < 16; i++)                                       \
                yb[BUF][i] = py[(size_t)((CH) * 16 + i) * ND];                 \
            _Pragma("unroll")                                                  \
            for (int i = 0; i < 16; i++)                                       \
                xb[BUF][i] = px[(size_t)((CH) * 16 + i) * ND];                 \
        }                                                                      \
    } while (0)

#define L2_COMPUTE(BUF, CH)                                                    \
    do {                                                                       \
        float ob[16];                                                          \
        _Pragma("unroll")                                                      \
        for (int i = 0; i < 16; i++) {                                         \
            v = v + (yb[BUF][i] - v) * 0.5f;                                   \
            bool sp = (v >= 1.0f);                                             \
            ob[i] = xb[BUF][i] + (sp ? 1.0f : 0.0f);                           \
            v = sp ? 0.f : v;                                                  \
        }                                                                      \
        _Pragma("unroll")                                                      \
        for (int i = 0; i < 16; i++)                                           \
            po[(size_t)((CH) * 16 + i) * ND] = ob[i];                          \
    } while (0)

__global__ __launch_bounds__(64) void lif2_kernel(const float* __restrict__ x,
                                                  float* __restrict__ out) {
    const int idx = blockIdx.x * 64 + threadIdx.x;    // NB*ND = 16384
    const int b = idx >> 9;
    const int d = idx & (ND - 1);
    const float* py = g_y + (size_t)b * NT * ND + d;
    const float* px = x + (size_t)b * NT * ND + d;
    float* po = out + (size_t)b * NT * ND + d;

    float yb[4][16], xb[4][16];
    L2_PREFETCH(0, 0);
    L2_PREFETCH(1, 1);

    float v = 0.f;
#pragma unroll 1
    for (int c = 0; c < 32; c += 4) {       // 8 iterations, 4 chunks each
        L2_PREFETCH(2, c + 2);
        L2_COMPUTE(0, c);
        L2_PREFETCH(3, c + 3);
        L2_COMPUTE(1, c + 1);
        L2_PREFETCH(0, c + 4);
        L2_COMPUTE(2, c + 2);
        L2_PREFETCH(1, c + 5);
        L2_COMPUTE(3, c + 3);
    }
}

// ============================================================================
extern "C" void kernel_launch(void* const* d_in, const int* in_sizes, int n_in,
                              void* d_out, int out_size) {
    const float* x   = (const float*)d_in[0];
    const float* w1  = (const float*)d_in[1];
    const float* b1  = (const float*)d_in[2];
    const float* g1  = (const float*)d_in[3];
    const float* be1 = (const float*)d_in[4];
    const float* w2  = (const float*)d_in[5];
    const float* b2  = (const float*)d_in[6];
    const float* g2  = (const float*)d_in[7];
    const float* be2 = (const float*)d_in[8];
    float* out = (float*)d_out;

    gemm1_kernel<<<dim3(NH / 128, NM / 128), 256>>>(x, w1, b1);
    ln1_stats_kernel<<<NM / 8 + 512, 256>>>(w2);   // stats + folded transpose
    lif1_kernel<<<(NB * NH) / 128, 128>>>(g1, be1);
    fc2ln2_kernel<<<NM, 128>>>(b2, g2, be2);
    lif2_kernel<<<(NB * ND) / 64, 64>>>(x, out);
}